// round 1
// baseline (speedup 1.0000x reference)
#include <cuda_runtime.h>

// Problem constants
#define NN   50000      // nodes
#define NE   100000     // edges
#define NG   2000       // graphs
#define DD   300        // hidden dim
#define DD2  600        // 2*D
#define NL   5          // layers
#define NT   10         // tasks
#define NUM_BOND 6
#define NUM_DIR  3

#define ND   (NN*DD)    // 15,000,000
#define ED   (NE*DD)    // 30,000,000

// ---------------- scratch (global device arrays; no allocation allowed) ----
__device__ float g_h[NN*DD];      // node features (layer input)
__device__ float g_agg[NN*DD];    // aggregated messages
__device__ float g_tmp[NN*DD2];   // after GEMM1+relu
__device__ float g_h2[NN*DD];     // after GEMM2
__device__ float g_sum[DD];
__device__ float g_sumsq[DD];
__device__ float g_mu[DD];
__device__ float g_rstd[DD];
__device__ float g_gsum[NG*DD];
__device__ float g_gcnt[NG];

// ---------------- kernels --------------------------------------------------

// h[n,d] = xemb1[x[n,0],d] + xemb2[x[n,1],d]
__global__ void k_init(const int* __restrict__ x,
                       const float* __restrict__ xemb1,
                       const float* __restrict__ xemb2) {
    int idx = blockIdx.x * blockDim.x + threadIdx.x;
    if (idx >= ND) return;
    int n = idx / DD, d = idx - n * DD;
    int a = x[2 * n], c = x[2 * n + 1];
    g_h[idx] = xemb1[a * DD + d] + xemb2[c * DD + d];
}

// agg[n,d] = h[n,d] + selfloop_emb[d]   (self-loop attr = [4,0])
__global__ void k_prep(const float* __restrict__ e1_sl,   // eemb1[l][4]
                       const float* __restrict__ e2_sl) { // eemb2[l][0]
    int idx = blockIdx.x * blockDim.x + threadIdx.x;
    if (idx >= ND) return;
    int d = idx % DD;
    g_agg[idx] = g_h[idx] + e1_sl[d] + e2_sl[d];
}

// for each real edge: agg[dst] += h[src] + eemb1[l][a0] + eemb2[l][a1]
__global__ void k_scatter(const int* __restrict__ ei,     // [2,E]
                          const int* __restrict__ ea,     // [E,2]
                          const float* __restrict__ e1l,  // eemb1[l] : [6,300]
                          const float* __restrict__ e2l)  // eemb2[l] : [3,300]
{
    int idx = blockIdx.x * blockDim.x + threadIdx.x;
    if (idx >= ED) return;
    int e = idx / DD, d = idx - e * DD;
    int src = ei[e];
    int dst = ei[NE + e];
    int a0 = ea[2 * e];
    int a1 = ea[2 * e + 1];
    float msg = g_h[src * DD + d] + e1l[a0 * DD + d] + e2l[a1 * DD + d];
    atomicAdd(&g_agg[dst * DD + d], msg);
}

// GEMM: MODE 0: g_tmp = relu(g_agg[N,300] @ B[300,600] + bias)
//       MODE 1: g_h2  =      g_tmp[N,600] @ B[600,300] + bias
// 64x64 tile, BK=8, 256 threads, 4x4 per-thread microtile.
template <int MODE>
__global__ void __launch_bounds__(256)
k_gemm(const float* __restrict__ B, const float* __restrict__ bias) {
    const int M  = NN;
    const int K  = (MODE == 0) ? DD : DD2;
    const int Nc = (MODE == 0) ? DD2 : DD;
    const float* __restrict__ A = (MODE == 0) ? g_agg : g_tmp;
    float* __restrict__ C       = (MODE == 0) ? g_tmp : g_h2;

    __shared__ float As[8][64];
    __shared__ float Bs[8][64];

    int tid = threadIdx.x;
    int row0 = blockIdx.y * 64;
    int col0 = blockIdx.x * 64;
    int tx = tid & 15, ty = tid >> 4;

    int a_k = tid & 7, a_m = tid >> 3;   // A loader: 32 rows x 8 k (x2)
    int b_n = tid & 63, b_k = tid >> 6;  // B loader: 4 k x 64 n   (x2)

    float acc[4][4] = {};

    for (int k0 = 0; k0 < K; k0 += 8) {
        // load A tile (guarded)
        {
            int k = k0 + a_k;
            float v0 = 0.f, v1 = 0.f;
            if (k < K) {
                int r0 = row0 + a_m;
                int r1 = r0 + 32;
                if (r0 < M) v0 = A[r0 * K + k];
                if (r1 < M) v1 = A[r1 * K + k];
            }
            As[a_k][a_m]      = v0;
            As[a_k][a_m + 32] = v1;
        }
        // load B tile (guarded)
        {
            int c = col0 + b_n;
            int k1 = k0 + b_k, k2 = k0 + b_k + 4;
            float v0 = 0.f, v1 = 0.f;
            if (c < Nc) {
                if (k1 < K) v0 = B[k1 * Nc + c];
                if (k2 < K) v1 = B[k2 * Nc + c];
            }
            Bs[b_k][b_n]     = v0;
            Bs[b_k + 4][b_n] = v1;
        }
        __syncthreads();
        #pragma unroll
        for (int k = 0; k < 8; ++k) {
            float4 a4 = *(const float4*)&As[k][ty * 4];
            float4 b4 = *(const float4*)&Bs[k][tx * 4];
            float ar[4] = {a4.x, a4.y, a4.z, a4.w};
            float br[4] = {b4.x, b4.y, b4.z, b4.w};
            #pragma unroll
            for (int i = 0; i < 4; ++i)
                #pragma unroll
                for (int j = 0; j < 4; ++j)
                    acc[i][j] += ar[i] * br[j];
        }
        __syncthreads();
    }

    #pragma unroll
    for (int i = 0; i < 4; ++i) {
        int r = row0 + ty * 4 + i;
        if (r >= M) continue;
        #pragma unroll
        for (int j = 0; j < 4; ++j) {
            int c = col0 + tx * 4 + j;
            if (c >= Nc) continue;
            float v = acc[i][j] + bias[c];
            if (MODE == 0) v = fmaxf(v, 0.f);
            C[r * Nc + c] = v;
        }
    }
}

__global__ void k_zero_stats() {
    int t = threadIdx.x;
    if (t < DD) { g_sum[t] = 0.f; g_sumsq[t] = 0.f; }
}

// per-block: 64 rows, all 300 cols -> partial col sums, atomic into g_sum/sq
__global__ void k_colstats() {
    int r0 = blockIdx.x * 64;
    int t = threadIdx.x; // 128
    float s0 = 0, s1 = 0, s2 = 0, q0 = 0, q1 = 0, q2 = 0;
    int rend = min(r0 + 64, NN);
    for (int r = r0; r < rend; ++r) {
        const float* row = g_h2 + r * DD;
        int c0 = t, c1 = t + 128, c2 = t + 256;
        float v0 = row[c0];         s0 += v0; q0 += v0 * v0;
        float v1 = row[c1];         s1 += v1; q1 += v1 * v1;
        if (c2 < DD) { float v2 = row[c2]; s2 += v2; q2 += v2 * v2; }
    }
    atomicAdd(&g_sum[t], s0);        atomicAdd(&g_sumsq[t], q0);
    atomicAdd(&g_sum[t + 128], s1);  atomicAdd(&g_sumsq[t + 128], q1);
    if (t + 256 < DD) { atomicAdd(&g_sum[t + 256], s2); atomicAdd(&g_sumsq[t + 256], q2); }
}

__global__ void k_finstats() {
    int d = threadIdx.x;
    if (d < DD) {
        float mu = g_sum[d] * (1.0f / NN);
        float var = g_sumsq[d] * (1.0f / NN) - mu * mu;
        g_mu[d] = mu;
        g_rstd[d] = rsqrtf(var + 1e-5f);
    }
}

// BN apply. mode 0: write g_h with relu (inner layers).
//           mode 1: write extOut, no relu (final layer -> node_rep output).
__global__ void k_bn(const float* __restrict__ gamma_l,
                     const float* __restrict__ beta_l,
                     float* __restrict__ extOut, int mode) {
    int idx = blockIdx.x * blockDim.x + threadIdx.x;
    if (idx >= ND) return;
    int d = idx % DD;
    float v = (g_h2[idx] - g_mu[d]) * g_rstd[d] * gamma_l[d] + beta_l[d];
    if (mode == 0) {
        g_h[idx] = fmaxf(v, 0.f);
    } else {
        extOut[idx] = v;
    }
}

__global__ void k_zero_pool() {
    int idx = blockIdx.x * blockDim.x + threadIdx.x;
    if (idx < NG * DD) g_gsum[idx] = 0.f;
    if (idx < NG) g_gcnt[idx] = 0.f;
}

__global__ void k_pool(const int* __restrict__ batch,
                       const float* __restrict__ rep) {
    int idx = blockIdx.x * blockDim.x + threadIdx.x;
    if (idx >= ND) return;
    int n = idx / DD, d = idx - n * DD;
    int b = batch[n];
    atomicAdd(&g_gsum[b * DD + d], rep[idx]);
    if (d == 0) atomicAdd(&g_gcnt[b], 1.0f);
}

// per graph: graph_rep = gsum / max(cnt,1); pred = graph_rep @ predW + predb
__global__ void k_pred(const float* __restrict__ predW,
                       const float* __restrict__ predb,
                       float* __restrict__ grep_out,
                       float* __restrict__ pred_out) {
    int g = blockIdx.x;
    __shared__ float rep[DD];
    float inv = 1.0f / fmaxf(g_gcnt[g], 1.0f);
    for (int d = threadIdx.x; d < DD; d += blockDim.x) {
        float v = g_gsum[g * DD + d] * inv;
        rep[d] = v;
        grep_out[g * DD + d] = v;
    }
    __syncthreads();
    if (threadIdx.x < NT) {
        int t = threadIdx.x;
        float acc = predb[t];
        for (int d = 0; d < DD; ++d) acc += rep[d] * predW[d * NT + t];
        pred_out[g * NT + t] = acc;
    }
}

// ---------------- host orchestration ---------------------------------------

static void run_gnn(const int* x, const int* ei, const int* ea, const int* batch,
                    const float* xemb1, const float* xemb2,
                    const float* eemb1, const float* eemb2,
                    const float* W1, const float* b1,
                    const float* W2, const float* b2,
                    const float* gamma, const float* beta,
                    const float* predW, const float* predb,
                    float* pred_out, float* grep_out, float* nrep_out) {
    const int BLK = 256;
    const int GRID_ND = (ND + BLK - 1) / BLK;
    const int GRID_ED = (ED + BLK - 1) / BLK;
    const int GRID_ROWS = (NN + 63) / 64;

    k_init<<<GRID_ND, BLK>>>(x, xemb1, xemb2);

    for (int l = 0; l < NL; ++l) {
        const float* e1l = eemb1 + (size_t)l * NUM_BOND * DD;
        const float* e2l = eemb2 + (size_t)l * NUM_DIR * DD;

        k_prep<<<GRID_ND, BLK>>>(e1l + 4 * DD, e2l);           // self-loops
        k_scatter<<<GRID_ED, BLK>>>(ei, ea, e1l, e2l);          // real edges

        k_gemm<0><<<dim3((DD2 + 63) / 64, GRID_ROWS), 256>>>(
            W1 + (size_t)l * DD * DD2, b1 + (size_t)l * DD2);
        k_gemm<1><<<dim3((DD + 63) / 64, GRID_ROWS), 256>>>(
            W2 + (size_t)l * DD2 * DD, b2 + (size_t)l * DD);

        k_zero_stats<<<1, 384>>>();
        k_colstats<<<GRID_ROWS, 128>>>();
        k_finstats<<<1, 384>>>();

        int last = (l == NL - 1);
        k_bn<<<GRID_ND, BLK>>>(gamma + (size_t)l * DD, beta + (size_t)l * DD,
                               nrep_out, last);
    }

    k_zero_pool<<<(NG * DD + BLK - 1) / BLK, BLK>>>();
    k_pool<<<GRID_ND, BLK>>>(batch, nrep_out);
    k_pred<<<NG, 128>>>(predW, predb, grep_out, pred_out);
}

extern "C" void kernel_launch(void* const* d_in, const int* in_sizes, int n_in,
                              void* d_out, int out_size) {
    const int*   x      = (const int*)d_in[0];
    const int*   ei     = (const int*)d_in[1];
    const int*   ea     = (const int*)d_in[2];
    const int*   batch  = (const int*)d_in[3];
    const int*   x1     = (const int*)d_in[4];
    const int*   ei1    = (const int*)d_in[5];
    const int*   ea1    = (const int*)d_in[6];
    const int*   batch1 = (const int*)d_in[7];
    const float* xemb1  = (const float*)d_in[8];
    const float* xemb2  = (const float*)d_in[9];
    const float* eemb1  = (const float*)d_in[10];
    const float* eemb2  = (const float*)d_in[11];
    const float* W1     = (const float*)d_in[12];
    const float* b1     = (const float*)d_in[13];
    const float* W2     = (const float*)d_in[14];
    const float* b2     = (const float*)d_in[15];
    const float* gamma  = (const float*)d_in[16];
    const float* beta   = (const float*)d_in[17];
    const float* predW  = (const float*)d_in[18];
    const float* predb  = (const float*)d_in[19];

    float* out = (float*)d_out;
    // layout: pred[2000*10] | graph_rep[2000*300] | node_rep[50000*300] | (repeat for graph 1)
    float* pred0 = out;
    float* grep0 = out + NG * NT;
    float* nrep0 = out + NG * NT + NG * DD;
    float* pred1 = out + NG * NT + NG * DD + (size_t)NN * DD;
    float* grep1 = pred1 + NG * NT;
    float* nrep1 = pred1 + NG * NT + NG * DD;

    run_gnn(x,  ei,  ea,  batch,  xemb1, xemb2, eemb1, eemb2,
            W1, b1, W2, b2, gamma, beta, predW, predb,
            pred0, grep0, nrep0);
    run_gnn(x1, ei1, ea1, batch1, xemb1, xemb2, eemb1, eemb2,
            W1, b1, W2, b2, gamma, beta, predW, predb,
            pred1, grep1, nrep1);
}

// round 2
// speedup vs baseline: 1.9292x; 1.9292x over previous
#include <cuda_runtime.h>

// Problem constants
#define NN   50000      // nodes
#define NE   100000     // edges
#define NG   2000       // graphs
#define DD   300        // hidden dim
#define DD2  600        // 2*D
#define NL   5          // layers
#define NT   10         // tasks
#define NUM_BOND 6
#define NUM_DIR  3

#define ND   (NN*DD)    // 15,000,000
#define ED   (NE*DD)    // 30,000,000

// ---------------- scratch (global device arrays; no allocation allowed) ----
__device__ float g_h[NN*DD];      // node features (layer input)
__device__ float g_agg[NN*DD];    // aggregated messages
__device__ float g_tmp[NN*DD2];   // after GEMM1+relu
__device__ float g_h2[NN*DD];     // after GEMM2
__device__ float g_sum[DD];
__device__ float g_sumsq[DD];
__device__ float g_mu[DD];
__device__ float g_rstd[DD];
__device__ float g_gsum[NG*DD];
__device__ float g_gcnt[NG];

// ---------------- kernels --------------------------------------------------

// h[n,d] = xemb1[x[n,0],d] + xemb2[x[n,1],d];  agg = h + selfloop_emb(layer0)
__global__ void k_init(const int* __restrict__ x,
                       const float* __restrict__ xemb1,
                       const float* __restrict__ xemb2,
                       const float* __restrict__ e1_sl,   // eemb1[0][4]
                       const float* __restrict__ e2_sl) { // eemb2[0][0]
    int idx = blockIdx.x * blockDim.x + threadIdx.x;
    if (idx >= ND) return;
    int n = idx / DD, d = idx - n * DD;
    int a = x[2 * n], c = x[2 * n + 1];
    float v = xemb1[a * DD + d] + xemb2[c * DD + d];
    g_h[idx] = v;
    g_agg[idx] = v + e1_sl[d] + e2_sl[d];
}

// for each real edge: agg[dst] += h[src] + eemb1[l][a0] + eemb2[l][a1]
__global__ void k_scatter(const int* __restrict__ ei,     // [2,E]
                          const int* __restrict__ ea,     // [E,2]
                          const float* __restrict__ e1l,  // eemb1[l] : [6,300]
                          const float* __restrict__ e2l)  // eemb2[l] : [3,300]
{
    int idx = blockIdx.x * blockDim.x + threadIdx.x;
    if (idx >= ED) return;
    int e = idx / DD, d = idx - e * DD;
    int src = __ldg(&ei[e]);
    int dst = __ldg(&ei[NE + e]);
    int a0 = __ldg(&ea[2 * e]);
    int a1 = __ldg(&ea[2 * e + 1]);
    float msg = g_h[src * DD + d] + e1l[a0 * DD + d] + e2l[a1 * DD + d];
    atomicAdd(&g_agg[dst * DD + d], msg);
}

// ---------------- high-intensity SGEMM -------------------------------------
// MODE 0: g_tmp = relu(g_agg[N,300] @ B[300,600] + bias)   TM=128 TN=128
// MODE 1: g_h2  =      g_tmp[N,600] @ B[600,300] + bias    TM=128 TN=64
// 8x8 microtile per thread, BK=8, double-buffered smem, reg prefetch.
template <int TN, int NTHREADS, int MODE>
__global__ void __launch_bounds__(NTHREADS)
k_gemm(const float* __restrict__ B, const float* __restrict__ bias) {
    constexpr int TM = 128, BK = 8;
    const int M  = NN;
    const int K  = (MODE == 0) ? DD : DD2;
    const int Nc = (MODE == 0) ? DD2 : DD;
    const float* __restrict__ A = (MODE == 0) ? g_agg : g_tmp;
    float* __restrict__ C       = (MODE == 0) ? g_tmp : g_h2;

    __shared__ float As[2][BK][TM];
    __shared__ float Bs[2][BK][TN];

    const int tid = threadIdx.x;
    const int tx  = tid % (TN / 8);
    const int ty  = tid / (TN / 8);
    const int row0 = blockIdx.y * TM;
    const int col0 = blockIdx.x * TN;

    constexpr int NA4 = TM * BK / 4;        // float4s in A tile
    constexpr int APT = NA4 / NTHREADS;     // per thread (1 or 2)
    constexpr int NB4 = BK * TN / 4;
    constexpr int BPT = NB4 / NTHREADS;     // 1

    const int nTiles = (K + BK - 1) / BK;

    float4 pa[APT], pb[BPT];

    auto ldgTile = [&](int t) {
        int k0 = t * BK;
        #pragma unroll
        for (int i = 0; i < APT; i++) {
            int a4 = tid + i * NTHREADS;
            int r  = a4 % TM;
            int kk = (a4 / TM) * 4;
            int gr = row0 + r, gk = k0 + kk;
            float4 v = make_float4(0.f, 0.f, 0.f, 0.f);
            if (gr < M && gk < K) v = *(const float4*)&A[(size_t)gr * K + gk];
            pa[i] = v;
        }
        #pragma unroll
        for (int i = 0; i < BPT; i++) {
            int b4 = tid + i * NTHREADS;
            int n4 = (b4 % (TN / 4)) * 4;
            int k  = b4 / (TN / 4);
            int gk = k0 + k, gc = col0 + n4;
            float4 v = make_float4(0.f, 0.f, 0.f, 0.f);
            if (gk < K && gc < Nc) v = *(const float4*)&B[(size_t)gk * Nc + gc];
            pb[i] = v;
        }
    };
    auto stsTile = [&](int buf) {
        #pragma unroll
        for (int i = 0; i < APT; i++) {
            int a4 = tid + i * NTHREADS;
            int r  = a4 % TM;
            int kk = (a4 / TM) * 4;
            As[buf][kk + 0][r] = pa[i].x;
            As[buf][kk + 1][r] = pa[i].y;
            As[buf][kk + 2][r] = pa[i].z;
            As[buf][kk + 3][r] = pa[i].w;
        }
        #pragma unroll
        for (int i = 0; i < BPT; i++) {
            int b4 = tid + i * NTHREADS;
            int n4 = (b4 % (TN / 4)) * 4;
            int k  = b4 / (TN / 4);
            *(float4*)&Bs[buf][k][n4] = pb[i];
        }
    };

    float acc[8][8] = {};

    ldgTile(0);
    stsTile(0);
    __syncthreads();

    for (int t = 0; t < nTiles; ++t) {
        int cur = t & 1;
        if (t + 1 < nTiles) ldgTile(t + 1);
        #pragma unroll
        for (int k = 0; k < BK; k++) {
            float a0[8], b0[8];
            *(float4*)&a0[0] = *(const float4*)&As[cur][k][ty * 8];
            *(float4*)&a0[4] = *(const float4*)&As[cur][k][ty * 8 + 4];
            *(float4*)&b0[0] = *(const float4*)&Bs[cur][k][tx * 8];
            *(float4*)&b0[4] = *(const float4*)&Bs[cur][k][tx * 8 + 4];
            #pragma unroll
            for (int i = 0; i < 8; i++)
                #pragma unroll
                for (int j = 0; j < 8; j++)
                    acc[i][j] += a0[i] * b0[j];
        }
        if (t + 1 < nTiles) stsTile(cur ^ 1);
        __syncthreads();
    }

    #pragma unroll
    for (int i = 0; i < 8; i++) {
        int r = row0 + ty * 8 + i;
        if (r >= M) continue;
        #pragma unroll
        for (int jj = 0; jj < 2; jj++) {
            int c = col0 + tx * 8 + jj * 4;
            if (c >= Nc) continue;
            float4 v;
            v.x = acc[i][jj * 4 + 0] + bias[c + 0];
            v.y = acc[i][jj * 4 + 1] + bias[c + 1];
            v.z = acc[i][jj * 4 + 2] + bias[c + 2];
            v.w = acc[i][jj * 4 + 3] + bias[c + 3];
            if (MODE == 0) {
                v.x = fmaxf(v.x, 0.f); v.y = fmaxf(v.y, 0.f);
                v.z = fmaxf(v.z, 0.f); v.w = fmaxf(v.w, 0.f);
            }
            *(float4*)&C[(size_t)r * Nc + c] = v;
        }
    }
}

__global__ void k_zero_stats() {
    int t = threadIdx.x;
    if (t < DD) { g_sum[t] = 0.f; g_sumsq[t] = 0.f; }
}

// per-block: 64 rows, all 300 cols -> partial col sums, atomic into g_sum/sq
__global__ void k_colstats() {
    int r0 = blockIdx.x * 64;
    int t = threadIdx.x; // 128
    float s0 = 0, s1 = 0, s2 = 0, q0 = 0, q1 = 0, q2 = 0;
    int rend = min(r0 + 64, NN);
    for (int r = r0; r < rend; ++r) {
        const float* row = g_h2 + (size_t)r * DD;
        int c2 = t + 256;
        float v0 = row[t];       s0 += v0; q0 += v0 * v0;
        float v1 = row[t + 128]; s1 += v1; q1 += v1 * v1;
        if (c2 < DD) { float v2 = row[c2]; s2 += v2; q2 += v2 * v2; }
    }
    atomicAdd(&g_sum[t], s0);        atomicAdd(&g_sumsq[t], q0);
    atomicAdd(&g_sum[t + 128], s1);  atomicAdd(&g_sumsq[t + 128], q1);
    if (t + 256 < DD) { atomicAdd(&g_sum[t + 256], s2); atomicAdd(&g_sumsq[t + 256], q2); }
}

__global__ void k_finstats() {
    int d = threadIdx.x;
    if (d < DD) {
        float mu = g_sum[d] * (1.0f / NN);
        float var = g_sumsq[d] * (1.0f / NN) - mu * mu;
        g_mu[d] = mu;
        g_rstd[d] = rsqrtf(var + 1e-5f);
    }
}

// BN apply, fused with next-layer self-loop prep.
// mode 0: g_h = relu(v); g_agg = relu(v) + sl_emb(next layer)
// mode 1: extOut = v (final layer -> node_rep output)
__global__ void k_bn(const float* __restrict__ gamma_l,
                     const float* __restrict__ beta_l,
                     const float* __restrict__ e1_sl,
                     const float* __restrict__ e2_sl,
                     float* __restrict__ extOut, int mode) {
    int idx = blockIdx.x * blockDim.x + threadIdx.x;
    if (idx >= ND) return;
    int d = idx % DD;
    float v = (g_h2[idx] - g_mu[d]) * g_rstd[d] * gamma_l[d] + beta_l[d];
    if (mode == 0) {
        float r = fmaxf(v, 0.f);
        g_h[idx] = r;
        g_agg[idx] = r + e1_sl[d] + e2_sl[d];
    } else {
        extOut[idx] = v;
    }
}

__global__ void k_zero_pool() {
    int idx = blockIdx.x * blockDim.x + threadIdx.x;
    if (idx < NG * DD) g_gsum[idx] = 0.f;
    if (idx < NG) g_gcnt[idx] = 0.f;
}

__global__ void k_pool(const int* __restrict__ batch,
                       const float* __restrict__ rep) {
    int idx = blockIdx.x * blockDim.x + threadIdx.x;
    if (idx >= ND) return;
    int n = idx / DD, d = idx - n * DD;
    int b = batch[n];
    atomicAdd(&g_gsum[b * DD + d], rep[idx]);
    if (d == 0) atomicAdd(&g_gcnt[b], 1.0f);
}

// per graph: graph_rep = gsum / max(cnt,1); pred = graph_rep @ predW + predb
__global__ void k_pred(const float* __restrict__ predW,
                       const float* __restrict__ predb,
                       float* __restrict__ grep_out,
                       float* __restrict__ pred_out) {
    int g = blockIdx.x;
    __shared__ float rep[DD];
    float inv = 1.0f / fmaxf(g_gcnt[g], 1.0f);
    for (int d = threadIdx.x; d < DD; d += blockDim.x) {
        float v = g_gsum[g * DD + d] * inv;
        rep[d] = v;
        grep_out[g * DD + d] = v;
    }
    __syncthreads();
    if (threadIdx.x < NT) {
        int t = threadIdx.x;
        float acc = predb[t];
        for (int d = 0; d < DD; ++d) acc += rep[d] * predW[d * NT + t];
        pred_out[g * NT + t] = acc;
    }
}

// ---------------- host orchestration ---------------------------------------

static void run_gnn(const int* x, const int* ei, const int* ea, const int* batch,
                    const float* xemb1, const float* xemb2,
                    const float* eemb1, const float* eemb2,
                    const float* W1, const float* b1,
                    const float* W2, const float* b2,
                    const float* gamma, const float* beta,
                    const float* predW, const float* predb,
                    float* pred_out, float* grep_out, float* nrep_out) {
    const int BLK = 256;
    const int GRID_ND = (ND + BLK - 1) / BLK;
    const int GRID_ED = (ED + BLK - 1) / BLK;
    const int GRID_ROWS = (NN + 63) / 64;
    const int GRID_M128 = (NN + 127) / 128;   // 391

    const float* e10 = eemb1;             // layer 0 tables
    const float* e20 = eemb2;
    k_init<<<GRID_ND, BLK>>>(x, xemb1, xemb2, e10 + 4 * DD, e20);

    for (int l = 0; l < NL; ++l) {
        const float* e1l = eemb1 + (size_t)l * NUM_BOND * DD;
        const float* e2l = eemb2 + (size_t)l * NUM_DIR * DD;

        k_scatter<<<GRID_ED, BLK>>>(ei, ea, e1l, e2l);

        k_gemm<128, 256, 0><<<dim3((DD2 + 127) / 128, GRID_M128), 256>>>(
            W1 + (size_t)l * DD * DD2, b1 + (size_t)l * DD2);
        k_gemm<64, 128, 1><<<dim3((DD + 63) / 64, GRID_M128), 128>>>(
            W2 + (size_t)l * DD2 * DD, b2 + (size_t)l * DD);

        k_zero_stats<<<1, 384>>>();
        k_colstats<<<GRID_ROWS, 128>>>();
        k_finstats<<<1, 384>>>();

        int last = (l == NL - 1);
        const float* e1n = eemb1 + (size_t)(last ? l : l + 1) * NUM_BOND * DD;
        const float* e2n = eemb2 + (size_t)(last ? l : l + 1) * NUM_DIR * DD;
        k_bn<<<GRID_ND, BLK>>>(gamma + (size_t)l * DD, beta + (size_t)l * DD,
                               e1n + 4 * DD, e2n, nrep_out, last);
    }

    k_zero_pool<<<(NG * DD + BLK - 1) / BLK, BLK>>>();
    k_pool<<<GRID_ND, BLK>>>(batch, nrep_out);
    k_pred<<<NG, 128>>>(predW, predb, grep_out, pred_out);
}

extern "C" void kernel_launch(void* const* d_in, const int* in_sizes, int n_in,
                              void* d_out, int out_size) {
    const int*   x      = (const int*)d_in[0];
    const int*   ei     = (const int*)d_in[1];
    const int*   ea     = (const int*)d_in[2];
    const int*   batch  = (const int*)d_in[3];
    const int*   x1     = (const int*)d_in[4];
    const int*   ei1    = (const int*)d_in[5];
    const int*   ea1    = (const int*)d_in[6];
    const int*   batch1 = (const int*)d_in[7];
    const float* xemb1  = (const float*)d_in[8];
    const float* xemb2  = (const float*)d_in[9];
    const float* eemb1  = (const float*)d_in[10];
    const float* eemb2  = (const float*)d_in[11];
    const float* W1     = (const float*)d_in[12];
    const float* b1     = (const float*)d_in[13];
    const float* W2     = (const float*)d_in[14];
    const float* b2     = (const float*)d_in[15];
    const float* gamma  = (const float*)d_in[16];
    const float* beta   = (const float*)d_in[17];
    const float* predW  = (const float*)d_in[18];
    const float* predb  = (const float*)d_in[19];

    float* out = (float*)d_out;
    float* pred0 = out;
    float* grep0 = out + NG * NT;
    float* nrep0 = out + NG * NT + NG * DD;
    float* pred1 = out + NG * NT + NG * DD + (size_t)NN * DD;
    float* grep1 = pred1 + NG * NT;
    float* nrep1 = pred1 + NG * NT + NG * DD;

    run_gnn(x,  ei,  ea,  batch,  xemb1, xemb2, eemb1, eemb2,
            W1, b1, W2, b2, gamma, beta, predW, predb,
            pred0, grep0, nrep0);
    run_gnn(x1, ei1, ea1, batch1, xemb1, xemb2, eemb1, eemb2,
            W1, b1, W2, b2, gamma, beta, predW, predb,
            pred1, grep1, nrep1);
}

// round 4
// speedup vs baseline: 3.4977x; 1.8131x over previous
#include <cuda_runtime.h>
#include <cuda_bf16.h>
#include <cstdint>

// Problem constants
#define NN   50000
#define NE   100000
#define NG   2000
#define DD   300
#define DD2  600
#define NL   5
#define NT   10
#define NUM_BOND 6
#define NUM_DIR  3
#define ND   (NN*DD)
#define ED   (NE*DD)

// Padded GEMM dims
#define MPAD 50048          // 391 * 128
#define K1P  320            // K of GEMM1 (300 padded)
#define K2P  640            // K of GEMM2 (600 padded)
#define N1P  640            // N of GEMM1 (600 padded)
#define N2P  384            // N of GEMM2 (300 padded)

// smem tile geometry: 128 rows x 32 bf16 (64B data), padded to 80B row stride
#define RS     80
#define MATB   (128*RS)        // 10240 bytes per matrix tile
#define STAGEB (4*MATB)        // Ahi, Alo, Bhi, Blo
#define MG_SMEM (2*STAGEB)     // double buffered: 81920

// ---------------- scratch ---------------------------------------------------
__device__ float g_h[ND];
__device__ float g_agg[ND];
__device__ float g_h2[ND];
__device__ __nv_bfloat16 g_Ahi[(size_t)MPAD * K1P];
__device__ __nv_bfloat16 g_Alo[(size_t)MPAD * K1P];
__device__ __nv_bfloat16 g_Thi[(size_t)MPAD * K2P];
__device__ __nv_bfloat16 g_Tlo[(size_t)MPAD * K2P];
__device__ __nv_bfloat16 g_W1hi[NL * N1P * K1P];
__device__ __nv_bfloat16 g_W1lo[NL * N1P * K1P];
__device__ __nv_bfloat16 g_W2hi[NL * N2P * K2P];
__device__ __nv_bfloat16 g_W2lo[NL * N2P * K2P];
__device__ float g_sum[DD], g_sumsq[DD], g_mu[DD], g_rstd[DD];
__device__ float g_gsum[NG * DD], g_gcnt[NG];

// ---------------- PTX helpers (baseline ISA only — no tcgen05!) -------------
__device__ __forceinline__ uint32_t smem_to_u32(const void* p) {
    uint32_t a;
    asm("{ .reg .u64 t; cvta.to.shared.u64 t, %1; cvt.u32.u64 %0, t; }" : "=r"(a) : "l"(p));
    return a;
}

#define LDMX4(r, addr) \
    asm volatile("ldmatrix.sync.aligned.m8n8.x4.shared.b16 {%0,%1,%2,%3}, [%4];" \
        : "=r"((r)[0]), "=r"((r)[1]), "=r"((r)[2]), "=r"((r)[3]) : "r"(addr))

#define MMA_BF16(d, a, b) \
    asm volatile("mma.sync.aligned.m16n8k16.row.col.f32.bf16.bf16.f32 " \
        "{%0,%1,%2,%3}, {%4,%5,%6,%7}, {%8,%9}, {%0,%1,%2,%3};" \
        : "+f"((d)[0]), "+f"((d)[1]), "+f"((d)[2]), "+f"((d)[3]) \
        : "r"((a)[0]), "r"((a)[1]), "r"((a)[2]), "r"((a)[3]), \
          "r"((b)[0]), "r"((b)[1]))

#define CP_ASYNC16(dst, src) \
    asm volatile("cp.async.ca.shared.global [%0], [%1], 16;" :: "r"(dst), "l"(src) : "memory")
#define CP_COMMIT() asm volatile("cp.async.commit_group;" ::: "memory")
#define CP_WAIT1()  asm volatile("cp.async.wait_group 1;" ::: "memory")
#define CP_WAIT0()  asm volatile("cp.async.wait_group 0;" ::: "memory")

// ---------------- elementwise / graph kernels -------------------------------

__global__ void k_init(const int* __restrict__ x,
                       const float* __restrict__ xemb1,
                       const float* __restrict__ xemb2,
                       const float* __restrict__ e1_sl,
                       const float* __restrict__ e2_sl) {
    int idx = blockIdx.x * blockDim.x + threadIdx.x;
    if (idx >= ND) return;
    int n = idx / DD, d = idx - n * DD;
    int a = x[2 * n], c = x[2 * n + 1];
    float v = xemb1[a * DD + d] + xemb2[c * DD + d];
    g_h[idx] = v;
    g_agg[idx] = v + e1_sl[d] + e2_sl[d];
}

__global__ void k_scatter(const int* __restrict__ ei,
                          const int* __restrict__ ea,
                          const float* __restrict__ e1l,
                          const float* __restrict__ e2l) {
    int idx = blockIdx.x * blockDim.x + threadIdx.x;
    if (idx >= ED) return;
    int e = idx / DD, d = idx - e * DD;
    int src = __ldg(&ei[e]);
    int dst = __ldg(&ei[NE + e]);
    int a0 = __ldg(&ea[2 * e]);
    int a1 = __ldg(&ea[2 * e + 1]);
    float msg = g_h[src * DD + d] + e1l[a0 * DD + d] + e2l[a1 * DD + d];
    atomicAdd(&g_agg[dst * DD + d], msg);
}

// split g_agg (fp32 [NN,300]) -> g_Ahi/g_Alo (bf16 [MPAD,320], zero-padded)
__global__ void k_split_agg() {
    int idx = blockIdx.x * blockDim.x + threadIdx.x;
    if (idx >= MPAD * (K1P / 2)) return;
    int m = idx / (K1P / 2);
    int k = (idx - m * (K1P / 2)) * 2;
    float v0 = 0.f, v1 = 0.f;
    if (m < NN && k < DD) {
        const float* p = g_agg + (size_t)m * DD + k;
        v0 = p[0]; v1 = p[1];
    }
    __nv_bfloat16 h0 = __float2bfloat16(v0);
    __nv_bfloat16 h1 = __float2bfloat16(v1);
    __nv_bfloat16 l0 = __float2bfloat16(v0 - __bfloat162float(h0));
    __nv_bfloat16 l1 = __float2bfloat16(v1 - __bfloat162float(h1));
    size_t o = (size_t)m * K1P + k;
    __nv_bfloat162 th; th.x = h0; th.y = h1;
    __nv_bfloat162 tl; tl.x = l0; tl.y = l1;
    *(__nv_bfloat162*)&g_Ahi[o] = th;
    *(__nv_bfloat162*)&g_Alo[o] = tl;
}

// split W1[l] (fp32 [300,600] row-major) -> bf16 [640,320] n-major (B^T layout)
__global__ void k_split_w1(const float* __restrict__ W1, int l) {
    int idx = blockIdx.x * blockDim.x + threadIdx.x;
    if (idx >= N1P * K1P) return;
    int n = idx / K1P, k = idx - n * K1P;
    const float* src = W1 + (size_t)l * DD * DD2;
    float v = (n < DD2 && k < DD) ? src[(size_t)k * DD2 + n] : 0.f;
    __nv_bfloat16 h = __float2bfloat16(v);
    g_W1hi[(size_t)l * N1P * K1P + idx] = h;
    g_W1lo[(size_t)l * N1P * K1P + idx] = __float2bfloat16(v - __bfloat162float(h));
}

// split W2[l] (fp32 [600,300] row-major) -> bf16 [384,640] n-major
__global__ void k_split_w2(const float* __restrict__ W2, int l) {
    int idx = blockIdx.x * blockDim.x + threadIdx.x;
    if (idx >= N2P * K2P) return;
    int n = idx / K2P, k = idx - n * K2P;
    const float* src = W2 + (size_t)l * DD2 * DD;
    float v = (n < DD && k < DD2) ? src[(size_t)k * DD + n] : 0.f;
    __nv_bfloat16 h = __float2bfloat16(v);
    g_W2hi[(size_t)l * N2P * K2P + idx] = h;
    g_W2lo[(size_t)l * N2P * K2P + idx] = __float2bfloat16(v - __bfloat162float(h));
}

// ---------------- mma.sync bf16-split GEMM ----------------------------------
// MODE 0: relu(Agg @ W1 + b1) -> split bf16 into g_Thi/g_Tlo (stride K2P)
// MODE 1: T @ W2 + b2 -> fp32 g_h2 [NN,300]
// 128x128 CTA tile, 8 warps (2x4), 64x32 warp tile, BK=32, 2-stage cp.async.
template <int MODE>
__global__ void __launch_bounds__(256)
k_mgemm(int l, const float* __restrict__ bias) {
    constexpr int KPAD = MODE ? K2P : K1P;
    constexpr int NC   = MODE ? DD  : DD2;
    constexpr int NCHUNK = KPAD / 32;
    const __nv_bfloat16* __restrict__ Ahi = MODE ? g_Thi : g_Ahi;
    const __nv_bfloat16* __restrict__ Alo = MODE ? g_Tlo : g_Alo;
    const __nv_bfloat16* __restrict__ Bhi =
        MODE ? (g_W2hi + (size_t)l * N2P * K2P) : (g_W1hi + (size_t)l * N1P * K1P);
    const __nv_bfloat16* __restrict__ Blo =
        MODE ? (g_W2lo + (size_t)l * N2P * K2P) : (g_W1lo + (size_t)l * N1P * K1P);

    extern __shared__ __align__(16) char smem[];
    const uint32_t sbase = smem_to_u32(smem);
    const int tid = threadIdx.x;
    const int wid = tid >> 5;
    const int lane = tid & 31;
    const int row0 = blockIdx.y * 128;
    const int col0 = blockIdx.x * 128;
    const int wm = wid & 1;        // 0..1  (64-row slab)
    const int wn = wid >> 1;       // 0..3  (32-col slab)
    const int lr = lane & 15;      // ldmatrix row
    const int lc = lane >> 4;      // ldmatrix 16B col group

    // issue cp.async for chunk c into buffer c&1
    auto issue = [&](int c) {
        const int buf = c & 1;
        const int k0 = c * 32;
        #pragma unroll
        for (int i = 0; i < 8; i++) {
            int u = tid + i * 256;          // 0..2047
            int mat = u >> 9;               // 0..3
            int r = (u >> 2) & 127;
            int c16 = u & 3;
            const __nv_bfloat16* gp;
            if (mat == 0)      gp = Ahi + (size_t)(row0 + r) * KPAD;
            else if (mat == 1) gp = Alo + (size_t)(row0 + r) * KPAD;
            else if (mat == 2) gp = Bhi + (size_t)(col0 + r) * KPAD;
            else               gp = Blo + (size_t)(col0 + r) * KPAD;
            gp += k0 + c16 * 8;
            uint32_t dst = sbase + buf * STAGEB + mat * MATB + r * RS + c16 * 16;
            CP_ASYNC16(dst, gp);
        }
        CP_COMMIT();
    };

    float acc[4][4][4] = {};

    issue(0);
    for (int c = 0; c < NCHUNK; c++) {
        if (c + 1 < NCHUNK) { issue(c + 1); CP_WAIT1(); }
        else                { CP_WAIT0(); }
        __syncthreads();
        const uint32_t sb = sbase + (c & 1) * STAGEB;
        #pragma unroll
        for (int s = 0; s < 2; s++) {
            uint32_t ahi[4][4], alo[4][4], bhi[4][2], blo[4][2];
            #pragma unroll
            for (int i = 0; i < 4; i++) {
                uint32_t ra = sb + (wm * 64 + i * 16 + lr) * RS + s * 32 + lc * 16;
                LDMX4(ahi[i], ra);
                LDMX4(alo[i], ra + MATB);
            }
            #pragma unroll
            for (int jp = 0; jp < 2; jp++) {
                uint32_t rb = sb + 2 * MATB + (wn * 32 + jp * 16 + lr) * RS + s * 32 + lc * 16;
                uint32_t t[4];
                LDMX4(t, rb);
                bhi[2 * jp][0] = t[0]; bhi[2 * jp + 1][0] = t[1];
                bhi[2 * jp][1] = t[2]; bhi[2 * jp + 1][1] = t[3];
                LDMX4(t, rb + MATB);
                blo[2 * jp][0] = t[0]; blo[2 * jp + 1][0] = t[1];
                blo[2 * jp][1] = t[2]; blo[2 * jp + 1][1] = t[3];
            }
            #pragma unroll
            for (int i = 0; i < 4; i++)
                #pragma unroll
                for (int j = 0; j < 4; j++) {
                    MMA_BF16(acc[i][j], ahi[i], bhi[j]);
                    MMA_BF16(acc[i][j], ahi[i], blo[j]);
                    MMA_BF16(acc[i][j], alo[i], bhi[j]);
                }
        }
        __syncthreads();
    }

    // epilogue
    #pragma unroll
    for (int i = 0; i < 4; i++) {
        #pragma unroll
        for (int j = 0; j < 4; j++) {
            #pragma unroll
            for (int h = 0; h < 2; h++) {
                int m = row0 + wm * 64 + i * 16 + (lane >> 2) + h * 8;
                int n = col0 + wn * 32 + j * 8 + (lane & 3) * 2;
                float v0 = acc[i][j][h * 2];
                float v1 = acc[i][j][h * 2 + 1];
                if (MODE == 0) {
                    if (n < NC) {
                        v0 = fmaxf(v0 + bias[n], 0.f);
                        v1 = fmaxf(v1 + bias[n + 1], 0.f);
                    } else { v0 = 0.f; v1 = 0.f; }
                    __nv_bfloat16 h0 = __float2bfloat16(v0);
                    __nv_bfloat16 h1 = __float2bfloat16(v1);
                    __nv_bfloat16 l0 = __float2bfloat16(v0 - __bfloat162float(h0));
                    __nv_bfloat16 l1 = __float2bfloat16(v1 - __bfloat162float(h1));
                    size_t o = (size_t)m * K2P + n;
                    __nv_bfloat162 th; th.x = h0; th.y = h1;
                    __nv_bfloat162 tl; tl.x = l0; tl.y = l1;
                    *(__nv_bfloat162*)&g_Thi[o] = th;
                    *(__nv_bfloat162*)&g_Tlo[o] = tl;
                } else {
                    if (m < NN && n < NC) {
                        float2 v; v.x = v0 + bias[n]; v.y = v1 + bias[n + 1];
                        *(float2*)&g_h2[(size_t)m * DD + n] = v;
                    }
                }
            }
        }
    }
}

// ---------------- BN / pool / pred ------------------------------------------

__global__ void k_zero_stats() {
    int t = threadIdx.x;
    if (t < DD) { g_sum[t] = 0.f; g_sumsq[t] = 0.f; }
}

__global__ void k_colstats() {
    int r0 = blockIdx.x * 64;
    int t = threadIdx.x; // 128
    float s0 = 0, s1 = 0, s2 = 0, q0 = 0, q1 = 0, q2 = 0;
    int rend = min(r0 + 64, NN);
    for (int r = r0; r < rend; ++r) {
        const float* row = g_h2 + (size_t)r * DD;
        int c2 = t + 256;
        float v0 = row[t];       s0 += v0; q0 += v0 * v0;
        float v1 = row[t + 128]; s1 += v1; q1 += v1 * v1;
        if (c2 < DD) { float v2 = row[c2]; s2 += v2; q2 += v2 * v2; }
    }
    atomicAdd(&g_sum[t], s0);        atomicAdd(&g_sumsq[t], q0);
    atomicAdd(&g_sum[t + 128], s1);  atomicAdd(&g_sumsq[t + 128], q1);
    if (t + 256 < DD) { atomicAdd(&g_sum[t + 256], s2); atomicAdd(&g_sumsq[t + 256], q2); }
}

__global__ void k_finstats() {
    int d = threadIdx.x;
    if (d < DD) {
        float mu = g_sum[d] * (1.0f / NN);
        float var = g_sumsq[d] * (1.0f / NN) - mu * mu;
        g_mu[d] = mu;
        g_rstd[d] = rsqrtf(var + 1e-5f);
    }
}

// BN apply; mode 0: g_h = relu(v), g_agg = relu(v)+sl; mode 1: extOut = v
__global__ void k_bn(const float* __restrict__ gamma_l,
                     const float* __restrict__ beta_l,
                     const float* __restrict__ e1_sl,
                     const float* __restrict__ e2_sl,
                     float* __restrict__ extOut, int mode) {
    int idx = blockIdx.x * blockDim.x + threadIdx.x;
    if (idx >= ND) return;
    int d = idx % DD;
    float v = (g_h2[idx] - g_mu[d]) * g_rstd[d] * gamma_l[d] + beta_l[d];
    if (mode == 0) {
        float r = fmaxf(v, 0.f);
        g_h[idx] = r;
        g_agg[idx] = r + e1_sl[d] + e2_sl[d];
    } else {
        extOut[idx] = v;
    }
}

__global__ void k_zero_pool() {
    int idx = blockIdx.x * blockDim.x + threadIdx.x;
    if (idx < NG * DD) g_gsum[idx] = 0.f;
    if (idx < NG) g_gcnt[idx] = 0.f;
}

__global__ void k_pool(const int* __restrict__ batch,
                       const float* __restrict__ rep) {
    int idx = blockIdx.x * blockDim.x + threadIdx.x;
    if (idx >= ND) return;
    int n = idx / DD, d = idx - n * DD;
    int b = batch[n];
    atomicAdd(&g_gsum[b * DD + d], rep[idx]);
    if (d == 0) atomicAdd(&g_gcnt[b], 1.0f);
}

__global__ void k_pred(const float* __restrict__ predW,
                       const float* __restrict__ predb,
                       float* __restrict__ grep_out,
                       float* __restrict__ pred_out) {
    int g = blockIdx.x;
    __shared__ float rep[DD];
    float inv = 1.0f / fmaxf(g_gcnt[g], 1.0f);
    for (int d = threadIdx.x; d < DD; d += blockDim.x) {
        float v = g_gsum[g * DD + d] * inv;
        rep[d] = v;
        grep_out[g * DD + d] = v;
    }
    __syncthreads();
    if (threadIdx.x < NT) {
        int t = threadIdx.x;
        float acc = predb[t];
        for (int d = 0; d < DD; ++d) acc += rep[d] * predW[d * NT + t];
        pred_out[g * NT + t] = acc;
    }
}

// ---------------- host orchestration ---------------------------------------

static void run_gnn(const int* x, const int* ei, const int* ea, const int* batch,
                    const float* xemb1, const float* xemb2,
                    const float* eemb1, const float* eemb2,
                    const float* b1, const float* b2,
                    const float* gamma, const float* beta,
                    const float* predW, const float* predb,
                    float* pred_out, float* grep_out, float* nrep_out) {
    const int BLK = 256;
    const int GRID_ND = (ND + BLK - 1) / BLK;
    const int GRID_ED = (ED + BLK - 1) / BLK;
    const int GRID_ROWS = (NN + 63) / 64;
    const int GRID_M = MPAD / 128;  // 391
    const int GRID_SPLIT = (MPAD * (K1P / 2) + BLK - 1) / BLK;

    k_init<<<GRID_ND, BLK>>>(x, xemb1, xemb2, eemb1 + 4 * DD, eemb2);

    for (int l = 0; l < NL; ++l) {
        const float* e1l = eemb1 + (size_t)l * NUM_BOND * DD;
        const float* e2l = eemb2 + (size_t)l * NUM_DIR * DD;

        k_scatter<<<GRID_ED, BLK>>>(ei, ea, e1l, e2l);
        k_split_agg<<<GRID_SPLIT, BLK>>>();

        k_mgemm<0><<<dim3(N1P / 128, GRID_M), 256, MG_SMEM>>>(l, b1 + (size_t)l * DD2);
        k_mgemm<1><<<dim3(N2P / 128, GRID_M), 256, MG_SMEM>>>(l, b2 + (size_t)l * DD);

        k_zero_stats<<<1, 384>>>();
        k_colstats<<<GRID_ROWS, 128>>>();
        k_finstats<<<1, 384>>>();

        int last = (l == NL - 1);
        const float* e1n = eemb1 + (size_t)(last ? l : l + 1) * NUM_BOND * DD;
        const float* e2n = eemb2 + (size_t)(last ? l : l + 1) * NUM_DIR * DD;
        k_bn<<<GRID_ND, BLK>>>(gamma + (size_t)l * DD, beta + (size_t)l * DD,
                               e1n + 4 * DD, e2n, nrep_out, last);
    }

    k_zero_pool<<<(NG * DD + BLK - 1) / BLK, BLK>>>();
    k_pool<<<GRID_ND, BLK>>>(batch, nrep_out);
    k_pred<<<NG, 128>>>(predW, predb, grep_out, pred_out);
}

extern "C" void kernel_launch(void* const* d_in, const int* in_sizes, int n_in,
                              void* d_out, int out_size) {
    const int*   x      = (const int*)d_in[0];
    const int*   ei     = (const int*)d_in[1];
    const int*   ea     = (const int*)d_in[2];
    const int*   batch  = (const int*)d_in[3];
    const int*   x1     = (const int*)d_in[4];
    const int*   ei1    = (const int*)d_in[5];
    const int*   ea1    = (const int*)d_in[6];
    const int*   batch1 = (const int*)d_in[7];
    const float* xemb1  = (const float*)d_in[8];
    const float* xemb2  = (const float*)d_in[9];
    const float* eemb1  = (const float*)d_in[10];
    const float* eemb2  = (const float*)d_in[11];
    const float* W1     = (const float*)d_in[12];
    const float* b1     = (const float*)d_in[13];
    const float* W2     = (const float*)d_in[14];
    const float* b2     = (const float*)d_in[15];
    const float* gamma  = (const float*)d_in[16];
    const float* beta   = (const float*)d_in[17];
    const float* predW  = (const float*)d_in[18];
    const float* predb  = (const float*)d_in[19];

    cudaFuncSetAttribute(k_mgemm<0>, cudaFuncAttributeMaxDynamicSharedMemorySize, MG_SMEM);
    cudaFuncSetAttribute(k_mgemm<1>, cudaFuncAttributeMaxDynamicSharedMemorySize, MG_SMEM);

    for (int l = 0; l < NL; ++l) {
        k_split_w1<<<(N1P * K1P + 255) / 256, 256>>>(W1, l);
        k_split_w2<<<(N2P * K2P + 255) / 256, 256>>>(W2, l);
    }

    float* out = (float*)d_out;
    float* pred0 = out;
    float* grep0 = out + NG * NT;
    float* nrep0 = out + NG * NT + NG * DD;
    float* pred1 = out + NG * NT + NG * DD + (size_t)NN * DD;
    float* grep1 = pred1 + NG * NT;
    float* nrep1 = pred1 + NG * NT + NG * DD;

    run_gnn(x,  ei,  ea,  batch,  xemb1, xemb2, eemb1, eemb2,
            b1, b2, gamma, beta, predW, predb, pred0, grep0, nrep0);
    run_gnn(x1, ei1, ea1, batch1, xemb1, xemb2, eemb1, eemb2,
            b1, b2, gamma, beta, predW, predb, pred1, grep1, nrep1);
}